// round 16
// baseline (speedup 1.0000x reference)
#include <cuda_runtime.h>
#include <stdint.h>

// Static graph dims
#define BTOT     16384
#define IN_DIM   512
#define NHID     128
#define NOUT     256
#define TB       64          // batch rows per block; thread handles rows lane, lane+32
#define NTHREADS 1024
#define NWARPS   32

#define LB_STRIDE 641        // 512 x + 128 H + 1 pad (odd -> conflict-free)
#define OS_STRIDE 257

#define EH_CAP 4096
#define EO_CAP 8192
#define MAXSZ  64            // degree histogram cap for assignment sort

// Smem layout offsets (bytes)
#define SM_LB     0
#define SM_HSEG   (TB * LB_STRIDE * 4)
#define SM_OSEG   (SM_HSEG + (4 * NHID + 4) * 4)
#define SM_HASN   (SM_OSEG + (4 * NOUT + 4) * 4)
#define SM_OASN   (SM_HASN + NHID * 4)
#define SM_EDGES  (SM_OASN + NOUT * 4)

// ---------------- fast math ----------------
__device__ __forceinline__ float ex2f(float x) {
    float r; asm("ex2.approx.ftz.f32 %0, %1;" : "=f"(r) : "f"(x)); return r;
}
__device__ __forceinline__ float rcpf(float x) {
    float r; asm("rcp.approx.ftz.f32 %0, %1;" : "=f"(r) : "f"(x)); return r;
}
__device__ __forceinline__ float tanh_hw(float z) {       // 1 MUFU op
    float r; asm("tanh.approx.f32 %0, %1;" : "=f"(r) : "f"(z)); return r;
}
__device__ __forceinline__ float tanh_acc(float z) {      // accurate final act
    float e = ex2f(fminf(2.885390082f * z, 126.f));
    return (e - 1.f) * rcpf(e + 1.f);
}

// ---------------- dual-row accumulation over act-sorted segments ------------
// [p0,p1) linear, [p1,p2) relu, [p2,p3) tanh, [p3,p4) sigmoid (w pre-halved):
// sigmoid(z) = 0.5*tanh(z/2) + 0.5 -> affine fold in epilogue.
__device__ __forceinline__ float2 node_accum2(const float* __restrict__ r0,
                                              const float* __restrict__ r1,
                                              const int2* __restrict__ edges,
                                              int p0, int p1, int p2, int p3, int p4) {
    float a0 = 0.f, a1 = 0.f;
    #pragma unroll 2
    for (int i = p0; i < p1; i++) {                       // linear
        int2 e = edges[i];
        float w = __int_as_float(e.y);
        a0 = fmaf(r0[e.x], w, a0);
        a1 = fmaf(r1[e.x], w, a1);
    }
    #pragma unroll 2
    for (int i = p1; i < p2; i++) {                       // relu
        int2 e = edges[i];
        float w = __int_as_float(e.y);
        a0 += fmaxf(r0[e.x] * w, 0.f);
        a1 += fmaxf(r1[e.x] * w, 0.f);
    }
    #pragma unroll 2
    for (int i = p2; i < p3; i++) {                       // tanh (1 MUFU)
        int2 e = edges[i];
        float w = __int_as_float(e.y);
        a0 += tanh_hw(r0[e.x] * w);
        a1 += tanh_hw(r1[e.x] * w);
    }
    float s0 = 0.f, s1 = 0.f;
    #pragma unroll 2
    for (int i = p3; i < p4; i++) {                       // sigmoid core (1 MUFU)
        int2 e = edges[i];
        float w = __int_as_float(e.y);
        s0 += tanh_hw(r0[e.x] * w);
        s1 += tanh_hw(r1[e.x] * w);
    }
    float half_nsig = 0.5f * (float)(p4 - p3);
    a0 += fmaf(0.5f, s0, half_nsig);
    a1 += fmaf(0.5f, s1, half_nsig);
    return make_float2(a0, a1);
}

// ---------------- single fused kernel ---------------------------------------
// Each block independently rebuilds CSR + act-grouped edges + balanced
// assignment in its own smem (scratch overlays the x region), then runs the
// batch-tile forward pass. No inter-kernel dependency, one launch total.
__global__ __launch_bounds__(NTHREADS, 1)
void wann_kernel(const float* __restrict__ x, float* __restrict__ out,
                 const float* __restrict__ wh, const float* __restrict__ wo,
                 const int* __restrict__ rows_h, const int* __restrict__ cols_h,
                 const int* __restrict__ acts_h,
                 const int* __restrict__ rows_o, const int* __restrict__ cols_o,
                 const int* __restrict__ acts_o,
                 int Eh, int Eo) {
    extern __shared__ char smraw[];
    float* lb      = (float*)(smraw + SM_LB);            // [TB][LB_STRIDE]
    int*   s_hseg  = (int*)  (smraw + SM_HSEG);
    int*   s_oseg  = (int*)  (smraw + SM_OSEG);
    int*   s_hasn  = (int*)  (smraw + SM_HASN);
    int*   s_oasn  = (int*)  (smraw + SM_OASN);
    int2*  se      = (int2*) (smraw + SM_EDGES);

    // Scratch (dead after prep) overlays lb
    int* s_hptr = (int*)lb;                  // [NHID+1]
    int* s_optr = s_hptr + (NHID + 1);       // [NOUT+1]
    int* s_deg  = s_optr + (NOUT + 1);       // [NHID+NOUT]
    int* s_base = s_deg + (NHID + NOUT);     // [MAXSZ]
    int* s_cur  = s_base + MAXSZ;            // [MAXSZ]

    const int tid  = threadIdx.x;
    const int warp = tid >> 5;
    const int lane = tid & 31;
    const int row0 = blockIdx.x * TB;

    // ===== Prep P1: edge-parallel CSR boundary scatter =====
    for (int i = tid; i < Eh; i += NTHREADS) {
        int r  = rows_h[i];
        int rp = (i == 0) ? -1 : rows_h[i - 1];
        for (int q = rp + 1; q <= r; q++) s_hptr[q] = i;
    }
    for (int i = tid; i < Eo; i += NTHREADS) {
        int r  = rows_o[i];
        int rp = (i == 0) ? -1 : rows_o[i - 1];
        for (int q = rp + 1; q <= r; q++) s_optr[q] = i;
    }
    if (tid == 0) {
        int rp = (Eh > 0) ? rows_h[Eh - 1] : -1;
        for (int q = rp + 1; q <= NHID; q++) s_hptr[q] = Eh;
        int ro = (Eo > 0) ? rows_o[Eo - 1] : -1;
        for (int q = ro + 1; q <= NOUT; q++) s_optr[q] = Eo;
        s_hseg[4 * NHID] = Eh;
        s_oseg[4 * NOUT] = Eh + Eo;
    }
    __syncthreads();

    // ===== Prep P2: warp-per-node act grouping directly into smem se =====
    for (int node = warp; node < NHID + NOUT; node += NWARPS) {
        bool hid = node < NHID;
        int  n   = hid ? node : node - NHID;
        const int*   cols = hid ? cols_h : cols_o;
        const int*   acts = hid ? acts_h : acts_o;
        const float* wsrc = hid ? wh : wo;
        int          off  = hid ? 0 : Eh;
        int*         seg  = hid ? s_hseg : s_oseg;
        int b0 = hid ? s_hptr[n] : s_optr[n];
        int b1 = hid ? s_hptr[n + 1] : s_optr[n + 1];
        if (lane == 0) s_deg[node] = b1 - b0;

        int c0 = 0, c1 = 0, c2 = 0, c3 = 0;
        for (int bb = b0; bb < b1; bb += 32) {
            int i = bb + lane;
            int a = (i < b1) ? acts[i] : -1;
            c0 += __popc(__ballot_sync(0xFFFFFFFFu, a == 1));
            c1 += __popc(__ballot_sync(0xFFFFFFFFu, a == 3));
            c2 += __popc(__ballot_sync(0xFFFFFFFFu, a == 2));
            c3 += __popc(__ballot_sync(0xFFFFFFFFu, a == 4));
        }
        int s0 = off + b0, s1 = s0 + c0, s2 = s1 + c1, s3 = s2 + c2;
        if (lane == 0) {
            seg[4 * n + 0] = s0; seg[4 * n + 1] = s1;
            seg[4 * n + 2] = s2; seg[4 * n + 3] = s3;
        }
        int o0 = s0, o1 = s1, o2 = s2, o3 = s3;
        for (int bb = b0; bb < b1; bb += 32) {
            int i = bb + lane;
            int   a  = (i < b1) ? acts[i] : -1;
            int   cv = (i < b1) ? cols[i] : 0;
            float wv = (i < b1) ? wsrc[i] : 0.f;
            unsigned m0 = __ballot_sync(0xFFFFFFFFu, a == 1);
            unsigned m1 = __ballot_sync(0xFFFFFFFFu, a == 3);
            unsigned m2 = __ballot_sync(0xFFFFFFFFu, a == 2);
            unsigned m3 = __ballot_sync(0xFFFFFFFFu, a == 4);
            unsigned below = (1u << lane) - 1u;
            if (a == 1)      se[o0 + __popc(m0 & below)] = make_int2(cv, __float_as_int(wv));
            else if (a == 3) se[o1 + __popc(m1 & below)] = make_int2(cv, __float_as_int(wv));
            else if (a == 2) se[o2 + __popc(m2 & below)] = make_int2(cv, __float_as_int(wv));
            else if (a == 4) se[o3 + __popc(m3 & below)] = make_int2(cv, __float_as_int(wv * 0.5f));
            o0 += __popc(m0); o1 += __popc(m1); o2 += __popc(m2); o3 += __popc(m3);
        }
    }
    __syncthreads();

    // ===== Prep P3: edge-balanced assignment (counting sort desc) =====
    // hidden set
    if (tid < MAXSZ) s_cur[tid] = 0;
    __syncthreads();
    int hsz = 0;
    if (tid < NHID) { hsz = min(s_deg[tid], MAXSZ - 1); atomicAdd(&s_cur[hsz], 1); }
    __syncthreads();
    if (tid == 0) { int acc = 0; for (int s = MAXSZ - 1; s >= 0; s--) { s_base[s] = acc; acc += s_cur[s]; } }
    __syncthreads();
    if (tid < MAXSZ) s_cur[tid] = 0;
    __syncthreads();
    if (tid < NHID) {
        int r = s_base[hsz] + atomicAdd(&s_cur[hsz], 1);
        int row = r >> 5, col = r & 31;
        int w = (row & 1) ? (31 - col) : col;
        s_hasn[w * (NHID / 32) + row] = tid;
    }
    __syncthreads();
    // output set
    if (tid < MAXSZ) s_cur[tid] = 0;
    __syncthreads();
    int osz = 0;
    if (tid < NOUT) { osz = min(s_deg[NHID + tid], MAXSZ - 1); atomicAdd(&s_cur[osz], 1); }
    __syncthreads();
    if (tid == 0) { int acc = 0; for (int s = MAXSZ - 1; s >= 0; s--) { s_base[s] = acc; acc += s_cur[s]; } }
    __syncthreads();
    if (tid < MAXSZ) s_cur[tid] = 0;
    __syncthreads();
    if (tid < NOUT) {
        int r = s_base[osz] + atomicAdd(&s_cur[osz], 1);
        int row = r >> 5, col = r & 31;
        int w = (row & 1) ? (31 - col) : col;
        s_oasn[w * (NOUT / 32) + row] = tid;
    }
    __syncthreads();    // scratch dead; lb region free for x

    // ===== Phase 0: stage x tile (64 rows x 128 float4) =====
    {
        const float4* x4 = (const float4*)(x + (size_t)row0 * IN_DIM);
        #pragma unroll
        for (int i = 0; i < (TB * IN_DIM / 4) / NTHREADS; i++) {
            int t  = tid + i * NTHREADS;
            int r  = t >> 7;
            int c4 = t & 127;
            float4 v = x4[r * 128 + c4];
            float* d = lb + r * LB_STRIDE + c4 * 4;
            d[0] = v.x; d[1] = v.y; d[2] = v.z; d[3] = v.w;
        }
    }
    __syncthreads();

    float* r0 = lb + lane * LB_STRIDE;
    float* r1 = lb + (lane + 32) * LB_STRIDE;

    // ===== Phase 1: hidden nodes, edge-balanced assignment =====
    #pragma unroll
    for (int j = 0; j < NHID / NWARPS; j++) {
        int h = s_hasn[warp * (NHID / NWARPS) + j];
        int4 s = *(const int4*)&s_hseg[4 * h];
        int  s4 = s_hseg[4 * h + 4];
        float2 v = node_accum2(r0, r1, se, s.x, s.y, s.z, s.w, s4);
        r0[IN_DIM + h] = v.x;
        r1[IN_DIM + h] = v.y;
    }
    __syncthreads();

    // ===== Phase 2: output nodes; accurate final tanh =====
    float v0[NOUT / NWARPS], v1[NOUT / NWARPS];
    int   oid[NOUT / NWARPS];
    #pragma unroll
    for (int j = 0; j < NOUT / NWARPS; j++) {
        int o = s_oasn[warp * (NOUT / NWARPS) + j];
        oid[j] = o;
        int4 s = *(const int4*)&s_oseg[4 * o];
        int  s4 = s_oseg[4 * o + 4];
        float2 acc = node_accum2(r0, r1, se, s.x, s.y, s.z, s.w, s4);
        v0[j] = tanh_acc(acc.x);
        v1[j] = tanh_acc(acc.y);
    }
    __syncthreads();    // all lb reads done -> reuse as out staging

    // ===== Phase 3a: stage outputs [TB][OS_STRIDE] =====
    #pragma unroll
    for (int j = 0; j < NOUT / NWARPS; j++) {
        int o = oid[j];
        lb[lane * OS_STRIDE + o]        = v0[j];
        lb[(lane + 32) * OS_STRIDE + o] = v1[j];
    }
    __syncthreads();

    // ===== Phase 3b: coalesced flush =====
    {
        float* orow = out + (size_t)row0 * NOUT;
        #pragma unroll
        for (int i = 0; i < (TB * NOUT) / NTHREADS; i++) {
            int t = tid + i * NTHREADS;
            int r = t >> 8;
            int c = t & 255;
            orow[r * NOUT + c] = lb[r * OS_STRIDE + c];
        }
    }
}

// ---------------- launch ----------------
extern "C" void kernel_launch(void* const* d_in, const int* in_sizes, int n_in,
                              void* d_out, int out_size) {
    const float* x      = (const float*)d_in[0];
    const float* wh     = (const float*)d_in[1];
    const float* wo     = (const float*)d_in[2];
    const int*   rows_h = (const int*)d_in[3];
    const int*   cols_h = (const int*)d_in[4];
    const int*   acts_h = (const int*)d_in[5];
    const int*   rows_o = (const int*)d_in[6];
    const int*   cols_o = (const int*)d_in[7];
    const int*   acts_o = (const int*)d_in[8];
    float*       out    = (float*)d_out;

    int Eh = in_sizes[1]; if (Eh > EH_CAP) Eh = EH_CAP;
    int Eo = in_sizes[2]; if (Eo > EO_CAP) Eo = EO_CAP;

    size_t smem = (size_t)SM_EDGES + (size_t)(Eh + Eo) * sizeof(int2);
    cudaFuncSetAttribute(wann_kernel, cudaFuncAttributeMaxDynamicSharedMemorySize, (int)smem);
    wann_kernel<<<BTOT / TB, NTHREADS, smem>>>(x, out, wh, wo,
                                               rows_h, cols_h, acts_h,
                                               rows_o, cols_o, acts_o, Eh, Eo);
}

// round 17
// speedup vs baseline: 1.4658x; 1.4658x over previous
#include <cuda_runtime.h>
#include <stdint.h>

// Static graph dims
#define BTOT     16384
#define IN_DIM   512
#define NHID     128
#define NOUT     256
#define TB       64          // batch rows per block; thread handles rows lane, lane+32
#define NTHREADS 1024
#define NWARPS   32

#define LB_STRIDE 641        // 512 x + 128 H + 1 pad (odd -> conflict-free)
#define OS_STRIDE 257

#define EH_CAP 4096
#define EO_CAP 8192
#define MAXSZ  64            // degree histogram cap for assignment sort

// Combined edge table: hidden edges [0,Eh), output edges [Eh, Eh+Eo).
// Per node grouped [linear, relu, tanh(w plain), sigmoid(w*=0.5)].
__device__ int2 g_edges[EH_CAP + EO_CAP];
__device__ __align__(16) int g_hseg[4 * NHID + 4];
__device__ __align__(16) int g_oseg[4 * NOUT + 4];
__device__ int g_hassign[NHID];     // [32][NHID/32] edge-balanced node->warp map
__device__ int g_oassign[NOUT];

// Smem layout offsets (bytes) for main kernel
#define SM_LB     0
#define SM_HSEG   (TB * LB_STRIDE * 4)
#define SM_OSEG   (SM_HSEG + (4 * NHID + 4) * 4)
#define SM_HASN   (SM_OSEG + (4 * NOUT + 4) * 4)
#define SM_OASN   (SM_HASN + NHID * 4)
#define SM_EDGES  (SM_OASN + NOUT * 4)

// ---------------- fast math ----------------
__device__ __forceinline__ float ex2f(float x) {
    float r; asm("ex2.approx.ftz.f32 %0, %1;" : "=f"(r) : "f"(x)); return r;
}
__device__ __forceinline__ float rcpf(float x) {
    float r; asm("rcp.approx.ftz.f32 %0, %1;" : "=f"(r) : "f"(x)); return r;
}
__device__ __forceinline__ float tanh_hw(float z) {       // 1 MUFU op
    float r; asm("tanh.approx.f32 %0, %1;" : "=f"(r) : "f"(z)); return r;
}
__device__ __forceinline__ float tanh_acc(float z) {      // accurate final act
    float e = ex2f(fminf(2.885390082f * z, 126.f));
    return (e - 1.f) * rcpf(e + 1.f);
}

// ---------------- warp-cooperative 32-ary lower_bound -----------------------
__device__ __forceinline__ int warp_lb(const int* __restrict__ a, int E, int v) {
    const unsigned FULL = 0xFFFFFFFFu;
    int lane = threadIdx.x & 31;
    int lo = 0, hi = E;
    while (hi - lo > 31) {
        int len = hi - lo;
        int idx = lo + (int)(((long long)(lane + 1) * len) / 33);
        int lt = (a[idx] < v) ? 1 : 0;
        unsigned m = __ballot_sync(FULL, lt);
        int cnt = __popc(m);
        int nlo = (cnt == 0)  ? lo : lo + (int)(((long long)cnt * len) / 33) + 1;
        int nhi = (cnt == 32) ? hi : lo + (int)(((long long)(cnt + 1) * len) / 33);
        lo = nlo; hi = nhi;
    }
    int idx = lo + lane;
    int ge = (idx < hi) ? (a[idx] >= v ? 1 : 0) : 1;
    unsigned m = __ballot_sync(FULL, ge);
    return lo + (__ffs(m) - 1);
}

// ---------------- prep: warp-per-node CSR + act grouping --------------------
// Group order: g0=act1(linear), g1=act3(relu), g2=act2(tanh, w plain),
// g3=act4(sigmoid, w*=0.5 for 0.5*tanh(z/2)+0.5 identity).
__global__ void prep_kernel(const float* __restrict__ wh, const float* __restrict__ wo,
                            const int* __restrict__ rows_h, const int* __restrict__ cols_h,
                            const int* __restrict__ acts_h,
                            const int* __restrict__ rows_o, const int* __restrict__ cols_o,
                            const int* __restrict__ acts_o,
                            int Eh, int Eo) {
    int node = blockIdx.x * 16 + (threadIdx.x >> 5);
    int lane = threadIdx.x & 31;
    bool hid = node < NHID;
    int  n   = hid ? node : node - NHID;

    const int*   rows = hid ? rows_h : rows_o;
    const int*   cols = hid ? cols_h : cols_o;
    const int*   acts = hid ? acts_h : acts_o;
    const float* wsrc = hid ? wh : wo;
    int          E    = hid ? Eh : Eo;
    int          off  = hid ? 0 : Eh;
    int*         seg  = hid ? g_hseg : g_oseg;

    int b0 = warp_lb(rows, E, n);
    int b1 = warp_lb(rows, E, n + 1);

    int c0 = 0, c1 = 0, c2 = 0, c3 = 0;
    for (int base = b0; base < b1; base += 32) {
        int i = base + lane;
        int a = (i < b1) ? acts[i] : -1;
        c0 += __popc(__ballot_sync(0xFFFFFFFFu, a == 1));
        c1 += __popc(__ballot_sync(0xFFFFFFFFu, a == 3));
        c2 += __popc(__ballot_sync(0xFFFFFFFFu, a == 2));
        c3 += __popc(__ballot_sync(0xFFFFFFFFu, a == 4));
    }
    int s0 = off + b0, s1 = s0 + c0, s2 = s1 + c1, s3 = s2 + c2;
    if (lane == 0) {
        seg[4 * n + 0] = s0; seg[4 * n + 1] = s1;
        seg[4 * n + 2] = s2; seg[4 * n + 3] = s3;
    }
    if (node == 0 && lane == 0)    g_hseg[4 * NHID] = Eh;
    if (node == NHID && lane == 0) g_oseg[4 * NOUT] = Eh + Eo;

    int o0 = s0, o1 = s1, o2 = s2, o3 = s3;
    for (int base = b0; base < b1; base += 32) {
        int i = base + lane;
        int   a  = (i < b1) ? acts[i] : -1;
        int   cv = (i < b1) ? cols[i] : 0;
        float wv = (i < b1) ? wsrc[i] : 0.f;
        unsigned m0 = __ballot_sync(0xFFFFFFFFu, a == 1);
        unsigned m1 = __ballot_sync(0xFFFFFFFFu, a == 3);
        unsigned m2 = __ballot_sync(0xFFFFFFFFu, a == 2);
        unsigned m3 = __ballot_sync(0xFFFFFFFFu, a == 4);
        unsigned below = (1u << lane) - 1u;
        if (a == 1)      g_edges[o0 + __popc(m0 & below)] = make_int2(cv, __float_as_int(wv));
        else if (a == 3) g_edges[o1 + __popc(m1 & below)] = make_int2(cv, __float_as_int(wv));
        else if (a == 2) g_edges[o2 + __popc(m2 & below)] = make_int2(cv, __float_as_int(wv));
        else if (a == 4) g_edges[o3 + __popc(m3 & below)] = make_int2(cv, __float_as_int(wv * 0.5f));
        o0 += __popc(m0); o1 += __popc(m1); o2 += __popc(m2); o3 += __popc(m3);
    }
}

// ---------------- assign: edge-balanced node->warp mapping ------------------
__global__ void assign_kernel() {
    __shared__ int base[MAXSZ];
    __shared__ int cur[MAXSZ];
    int t = threadIdx.x;

    // hidden set
    if (t < MAXSZ) cur[t] = 0;
    __syncthreads();
    int hsz = 0;
    if (t < NHID) {
        hsz = min(g_hseg[4 * t + 4] - g_hseg[4 * t], MAXSZ - 1);
        atomicAdd(&cur[hsz], 1);
    }
    __syncthreads();
    if (t == 0) { int acc = 0; for (int s = MAXSZ - 1; s >= 0; s--) { base[s] = acc; acc += cur[s]; } }
    __syncthreads();
    if (t < MAXSZ) cur[t] = 0;
    __syncthreads();
    if (t < NHID) {
        int r = base[hsz] + atomicAdd(&cur[hsz], 1);
        int row = r >> 5, col = r & 31;
        int w = (row & 1) ? (31 - col) : col;
        g_hassign[w * (NHID / 32) + row] = t;
    }
    __syncthreads();
    // output set
    if (t < MAXSZ) cur[t] = 0;
    __syncthreads();
    int osz = 0;
    if (t < NOUT) {
        osz = min(g_oseg[4 * t + 4] - g_oseg[4 * t], MAXSZ - 1);
        atomicAdd(&cur[osz], 1);
    }
    __syncthreads();
    if (t == 0) { int acc = 0; for (int s = MAXSZ - 1; s >= 0; s--) { base[s] = acc; acc += cur[s]; } }
    __syncthreads();
    if (t < MAXSZ) cur[t] = 0;
    __syncthreads();
    if (t < NOUT) {
        int r = base[osz] + atomicAdd(&cur[osz], 1);
        int row = r >> 5, col = r & 31;
        int w = (row & 1) ? (31 - col) : col;
        g_oassign[w * (NOUT / 32) + row] = t;
    }
}

// ---------------- dual-row accumulation over act-sorted segments ------------
// [p0,p1) linear, [p1,p2) relu, [p2,p3) tanh, [p3,p4) sigmoid (w pre-halved):
// sigmoid(z) = 0.5*tanh(z/2) + 0.5 -> affine fold in epilogue.
__device__ __forceinline__ float2 node_accum2(const float* __restrict__ r0,
                                              const float* __restrict__ r1,
                                              const int2* __restrict__ edges,
                                              int p0, int p1, int p2, int p3, int p4) {
    float a0 = 0.f, a1 = 0.f;
    #pragma unroll 2
    for (int i = p0; i < p1; i++) {                       // linear
        int2 e = edges[i];
        float w = __int_as_float(e.y);
        a0 = fmaf(r0[e.x], w, a0);
        a1 = fmaf(r1[e.x], w, a1);
    }
    #pragma unroll 2
    for (int i = p1; i < p2; i++) {                       // relu
        int2 e = edges[i];
        float w = __int_as_float(e.y);
        a0 += fmaxf(r0[e.x] * w, 0.f);
        a1 += fmaxf(r1[e.x] * w, 0.f);
    }
    #pragma unroll 2
    for (int i = p2; i < p3; i++) {                       // tanh (1 MUFU)
        int2 e = edges[i];
        float w = __int_as_float(e.y);
        a0 += tanh_hw(r0[e.x] * w);
        a1 += tanh_hw(r1[e.x] * w);
    }
    float s0 = 0.f, s1 = 0.f;
    #pragma unroll 2
    for (int i = p3; i < p4; i++) {                       // sigmoid core (1 MUFU)
        int2 e = edges[i];
        float w = __int_as_float(e.y);
        s0 += tanh_hw(r0[e.x] * w);
        s1 += tanh_hw(r1[e.x] * w);
    }
    float half_nsig = 0.5f * (float)(p4 - p3);
    a0 += fmaf(0.5f, s0, half_nsig);
    a1 += fmaf(0.5f, s1, half_nsig);
    return make_float2(a0, a1);
}

// ---------------- main kernel ----------------
__global__ __launch_bounds__(NTHREADS, 1)
void wann_kernel(const float* __restrict__ x, float* __restrict__ out,
                 int Eh, int Eo) {
    extern __shared__ char smraw[];
    float* lb      = (float*)(smraw + SM_LB);            // [TB][LB_STRIDE]
    int*   s_hseg  = (int*)  (smraw + SM_HSEG);
    int*   s_oseg  = (int*)  (smraw + SM_OSEG);
    int*   s_hasn  = (int*)  (smraw + SM_HASN);
    int*   s_oasn  = (int*)  (smraw + SM_OASN);
    int2*  se      = (int2*) (smraw + SM_EDGES);

    const int tid  = threadIdx.x;
    const int warp = tid >> 5;
    const int lane = tid & 31;
    const int row0 = blockIdx.x * TB;
    const int Etot = Eh + Eo;

    // Phase 0a: copy metadata + edges into smem
    for (int i = tid; i < 4 * NHID + 4; i += NTHREADS) s_hseg[i] = g_hseg[i];
    for (int i = tid; i < 4 * NOUT + 4; i += NTHREADS) s_oseg[i] = g_oseg[i];
    for (int i = tid; i < NHID; i += NTHREADS) s_hasn[i] = g_hassign[i];
    for (int i = tid; i < NOUT; i += NTHREADS) s_oasn[i] = g_oassign[i];
    for (int i = tid; i < Etot; i += NTHREADS) se[i] = g_edges[i];

    // Phase 0b: stage x tile (64 rows x 128 float4)
    {
        const float4* x4 = (const float4*)(x + (size_t)row0 * IN_DIM);
        #pragma unroll
        for (int i = 0; i < (TB * IN_DIM / 4) / NTHREADS; i++) {
            int t  = tid + i * NTHREADS;
            int r  = t >> 7;
            int c4 = t & 127;
            float4 v = x4[r * 128 + c4];
            float* d = lb + r * LB_STRIDE + c4 * 4;
            d[0] = v.x; d[1] = v.y; d[2] = v.z; d[3] = v.w;
        }
    }
    __syncthreads();

    float* r0 = lb + lane * LB_STRIDE;
    float* r1 = lb + (lane + 32) * LB_STRIDE;

    // Phase 1: hidden nodes, edge-balanced assignment
    #pragma unroll
    for (int j = 0; j < NHID / NWARPS; j++) {
        int h = s_hasn[warp * (NHID / NWARPS) + j];
        int4 s = *(const int4*)&s_hseg[4 * h];
        int  s4 = s_hseg[4 * h + 4];
        float2 v = node_accum2(r0, r1, se, s.x, s.y, s.z, s.w, s4);
        r0[IN_DIM + h] = v.x;
        r1[IN_DIM + h] = v.y;
    }
    __syncthreads();

    // Phase 2: output nodes; accurate final tanh
    float v0[NOUT / NWARPS], v1[NOUT / NWARPS];
    int   oid[NOUT / NWARPS];
    #pragma unroll
    for (int j = 0; j < NOUT / NWARPS; j++) {
        int o = s_oasn[warp * (NOUT / NWARPS) + j];
        oid[j] = o;
        int4 s = *(const int4*)&s_oseg[4 * o];
        int  s4 = s_oseg[4 * o + 4];
        float2 acc = node_accum2(r0, r1, se, s.x, s.y, s.z, s.w, s4);
        v0[j] = tanh_acc(acc.x);
        v1[j] = tanh_acc(acc.y);
    }
    __syncthreads();    // all lb reads done -> reuse as out staging

    // Phase 3a: stage outputs [TB][OS_STRIDE]
    #pragma unroll
    for (int j = 0; j < NOUT / NWARPS; j++) {
        int o = oid[j];
        lb[lane * OS_STRIDE + o]        = v0[j];
        lb[(lane + 32) * OS_STRIDE + o] = v1[j];
    }
    __syncthreads();

    // Phase 3b: coalesced flush
    {
        float* orow = out + (size_t)row0 * NOUT;
        #pragma unroll
        for (int i = 0; i < (TB * NOUT) / NTHREADS; i++) {
            int t = tid + i * NTHREADS;
            int r = t >> 8;
            int c = t & 255;
            orow[r * NOUT + c] = lb[r * OS_STRIDE + c];
        }
    }
}

// ---------------- launch ----------------
extern "C" void kernel_launch(void* const* d_in, const int* in_sizes, int n_in,
                              void* d_out, int out_size) {
    const float* x      = (const float*)d_in[0];
    const float* wh     = (const float*)d_in[1];
    const float* wo     = (const float*)d_in[2];
    const int*   rows_h = (const int*)d_in[3];
    const int*   cols_h = (const int*)d_in[4];
    const int*   acts_h = (const int*)d_in[5];
    const int*   rows_o = (const int*)d_in[6];
    const int*   cols_o = (const int*)d_in[7];
    const int*   acts_o = (const int*)d_in[8];
    float*       out    = (float*)d_out;

    int Eh = in_sizes[1]; if (Eh > EH_CAP) Eh = EH_CAP;
    int Eo = in_sizes[2]; if (Eo > EO_CAP) Eo = EO_CAP;

    prep_kernel<<<(NHID + NOUT) / 16, 512>>>(wh, wo, rows_h, cols_h, acts_h,
                                             rows_o, cols_o, acts_o, Eh, Eo);
    assign_kernel<<<1, 512>>>();

    size_t smem = (size_t)SM_EDGES + (size_t)(Eh + Eo) * sizeof(int2);
    cudaFuncSetAttribute(wann_kernel, cudaFuncAttributeMaxDynamicSharedMemorySize, (int)smem);
    wann_kernel<<<BTOT / TB, NTHREADS, smem>>>(x, out, Eh, Eo);
}